// round 13
// baseline (speedup 1.0000x reference)
#include <cuda_runtime.h>
#include <cuda_fp16.h>
#include <mma.h>
#include <cstdint>

using namespace nvcuda;

#define D 128
#define MAX_NODES 100032
#define SLOTS 96                 // Poisson(32) tail beyond 96: ~e^-41, spill-guarded
#define MAX_SPILL 65536
#define WFIX_SCALE 32767.0f

// ---- device scratch (static globals; allocation-free) ----
__device__ uint4    g_h[(size_t)MAX_NODES * 16];          // 25.6 MB, fp16 h
__device__ unsigned g_csr[(size_t)MAX_NODES * SLOTS];     // 38.4 MB packed CSR
                                                          // entry = (col<<15)|wfix15
__device__ int      g_cnt[MAX_NODES];                     // degrees; re-zeroed by agg
__device__ int4     g_spill[MAX_SPILL];                   // (row, col, wbits_f32, 0)
__device__ int      g_spill_cnt;                          // starts 0; reset by fix kernel

// ---------------------------------------------------------------------------
// Tensor-core GEMM: h = x @ W^T, fp16 in (converted in-flight), fp32 acc,
// fp16 out. 128x128 block tile, 8 warps (4M x 2N), 2x4 wmma frags per warp.
// ---------------------------------------------------------------------------
__global__ __launch_bounds__(256) void gemm_tc_kernel(const float* __restrict__ x,
                                                      const float* __restrict__ W,
                                                      int n_rows) {
    __shared__ __align__(32) __half ws[128][136];   // ws[n][k] = W[n][k]
    __shared__ __align__(32) __half xs[128][24];

    const int tid = threadIdx.x;
    const int warp = tid >> 5;
    const int lane = tid & 31;
    const int block_row = blockIdx.x * 128;
    const int wm = warp & 3;
    const int wn = warp >> 2;

    for (int q = tid; q < 128 * 32; q += 256) {
        const int r = q >> 5;
        const int c4 = q & 31;
        const float4 v = ((const float4*)(W + (size_t)r * D))[c4];
        const __half2 h0 = __floats2half2_rn(v.x, v.y);
        const __half2 h1 = __floats2half2_rn(v.z, v.w);
        uint2 pk;
        pk.x = *reinterpret_cast<const unsigned*>(&h0);
        pk.y = *reinterpret_cast<const unsigned*>(&h1);
        *(uint2*)&ws[r][c4 * 4] = pk;
    }

    wmma::fragment<wmma::accumulator, 16, 16, 16, float> c[2][4];
#pragma unroll
    for (int mi = 0; mi < 2; mi++)
#pragma unroll
        for (int ni = 0; ni < 4; ni++)
            wmma::fill_fragment(c[mi][ni], 0.f);

    for (int kt = 0; kt < 8; kt++) {
        const int k0 = kt * 16;
        __syncthreads();
        {
            const int row = tid >> 1;
            const int seg = (tid & 1) * 8;
            float4 v0 = make_float4(0.f, 0.f, 0.f, 0.f);
            float4 v1 = v0;
            const int gr = block_row + row;
            if (gr < n_rows) {
                const float* p = x + (size_t)gr * D + k0 + seg;
                v0 = *(const float4*)p;
                v1 = *(const float4*)(p + 4);
            }
            const __half2 a0 = __floats2half2_rn(v0.x, v0.y);
            const __half2 a1 = __floats2half2_rn(v0.z, v0.w);
            const __half2 a2 = __floats2half2_rn(v1.x, v1.y);
            const __half2 a3 = __floats2half2_rn(v1.z, v1.w);
            uint4 pk;
            pk.x = *reinterpret_cast<const unsigned*>(&a0);
            pk.y = *reinterpret_cast<const unsigned*>(&a1);
            pk.z = *reinterpret_cast<const unsigned*>(&a2);
            pk.w = *reinterpret_cast<const unsigned*>(&a3);
            *(uint4*)&xs[row][seg] = pk;
        }
        __syncthreads();

        wmma::fragment<wmma::matrix_a, 16, 16, 16, __half, wmma::row_major> a[2];
        wmma::fragment<wmma::matrix_b, 16, 16, 16, __half, wmma::col_major> b[4];
#pragma unroll
        for (int mi = 0; mi < 2; mi++)
            wmma::load_matrix_sync(a[mi], &xs[wm * 32 + mi * 16][0], 24);
#pragma unroll
        for (int ni = 0; ni < 4; ni++)
            wmma::load_matrix_sync(b[ni], &ws[wn * 64 + ni * 16][k0], 136);
#pragma unroll
        for (int mi = 0; mi < 2; mi++)
#pragma unroll
            for (int ni = 0; ni < 4; ni++)
                wmma::mma_sync(c[mi][ni], a[mi], b[ni], c[mi][ni]);
    }

    __syncthreads();
    float* stage = (float*)ws + warp * 320;  // 16x20 floats, ld=20 (80B, legal)
    __half* hbase = (__half*)g_h;
#pragma unroll
    for (int mi = 0; mi < 2; mi++) {
#pragma unroll
        for (int ni = 0; ni < 4; ni++) {
            wmma::store_matrix_sync(stage, c[mi][ni], 20, wmma::mem_row_major);
            __syncwarp();
            const int r = lane >> 1;
            const int c8 = (lane & 1) * 8;
            const float* sp = stage + r * 20 + c8;
            const __half2 h0 = __floats2half2_rn(sp[0], sp[1]);
            const __half2 h1 = __floats2half2_rn(sp[2], sp[3]);
            const __half2 h2 = __floats2half2_rn(sp[4], sp[5]);
            const __half2 h3 = __floats2half2_rn(sp[6], sp[7]);
            uint4 pk;
            pk.x = *reinterpret_cast<const unsigned*>(&h0);
            pk.y = *reinterpret_cast<const unsigned*>(&h1);
            pk.z = *reinterpret_cast<const unsigned*>(&h2);
            pk.w = *reinterpret_cast<const unsigned*>(&h3);
            const int gr = block_row + wm * 32 + mi * 16 + r;
            const int col = wn * 64 + ni * 16 + c8;
            if (gr < n_rows)
                *(uint4*)(hbase + (size_t)gr * D + col) = pk;
            __syncwarp();
        }
    }
}

// ---------------------------------------------------------------------------
// fill_direct: single-pass bucketed CSR build with 4B packed entries.
// ---------------------------------------------------------------------------
__device__ __forceinline__ void fill_one(int row, int col, float w, int n_nodes) {
    if ((unsigned)row >= (unsigned)n_nodes || (unsigned)col >= (unsigned)n_nodes)
        return;
    const int pos = atomicAdd(&g_cnt[row], 1);
    if (pos < SLOTS) {
        const unsigned wfix = (unsigned)__float2int_rn(w * WFIX_SCALE) & 0x7FFFu;
        const unsigned entry = ((unsigned)col << 15) | wfix;
        unsigned* dst = &g_csr[(size_t)row * SLOTS + pos];
        asm volatile("st.global.cs.u32 [%0], %1;" :: "l"(dst), "r"(entry) : "memory");
    } else {
        const int sp = atomicAdd(&g_spill_cnt, 1);
        if (sp < MAX_SPILL)
            g_spill[sp] = make_int4(row, col, __float_as_int(w), 0);
    }
}

__global__ __launch_bounds__(256) void fill_direct_kernel(const int* __restrict__ edges,
                                                          const float* __restrict__ wts,
                                                          int n_edges, int n_nodes) {
    const int nq = n_edges >> 2;
    const int q = blockIdx.x * blockDim.x + threadIdx.x;
    if (q < nq) {
        const int4 r = ((const int4*)edges)[q];
        const int4 c = ((const int4*)(edges + n_edges))[q];
        const float4 w4 = ((const float4*)wts)[q];
        fill_one(r.x, c.x, w4.x, n_nodes);
        fill_one(r.y, c.y, w4.y, n_nodes);
        fill_one(r.z, c.z, w4.z, n_nodes);
        fill_one(r.w, c.w, w4.w, n_nodes);
    }
    if (blockIdx.x == 0 && (int)threadIdx.x < (n_edges & 3)) {
        const int e = (nq << 2) + threadIdx.x;
        fill_one(edges[e], edges[n_edges + e], wts[e], n_nodes);
    }
}

// ---------------------------------------------------------------------------
// agg: one warp per node; 32 packed entries batch-loaded per 128B coalesced
// read, shfl-distributed (1 shfl per entry). Unroll x4, 2 accumulators.
// ---------------------------------------------------------------------------
__device__ __forceinline__ uint2 ldg_nc_u2(const uint2* p) {
    uint2 v;
    asm volatile("ld.global.nc.v2.u32 {%0, %1}, [%2];"
                 : "=r"(v.x), "=r"(v.y) : "l"(p));
    return v;
}

__global__ __launch_bounds__(256) void agg_kernel(float* __restrict__ out, int n_nodes) {
    const int lane = threadIdx.x & 31;
    const int node = (blockIdx.x * blockDim.x + threadIdx.x) >> 5;
    if (node >= n_nodes) return;

    const int cnt = g_cnt[node];
    const int e = min(cnt, SLOTS);
    const size_t base0 = (size_t)node * SLOTS;

    float4 acc0 = make_float4(0.f, 0.f, 0.f, 0.f);
    float4 acc1 = make_float4(0.f, 0.f, 0.f, 0.f);

    for (int base = 0; base < e; base += 32) {
        const int n = min(32, e - base);
        unsigned cw = 0;
        if (lane < n) cw = g_csr[base0 + base + lane];

        int j = 0;
        for (; j + 4 <= n; j += 4) {
            const unsigned e0 = __shfl_sync(0xffffffffu, cw, j);
            const unsigned e1 = __shfl_sync(0xffffffffu, cw, j + 1);
            const unsigned e2 = __shfl_sync(0xffffffffu, cw, j + 2);
            const unsigned e3 = __shfl_sync(0xffffffffu, cw, j + 3);

            const uint2 p0 = ldg_nc_u2(((const uint2*)(g_h + (size_t)(e0 >> 15) * 16)) + lane);
            const uint2 p1 = ldg_nc_u2(((const uint2*)(g_h + (size_t)(e1 >> 15) * 16)) + lane);
            const uint2 p2 = ldg_nc_u2(((const uint2*)(g_h + (size_t)(e2 >> 15) * 16)) + lane);
            const uint2 p3 = ldg_nc_u2(((const uint2*)(g_h + (size_t)(e3 >> 15) * 16)) + lane);

            const float w0 = (float)(e0 & 0x7FFFu) * (1.0f / WFIX_SCALE);
            const float w1 = (float)(e1 & 0x7FFFu) * (1.0f / WFIX_SCALE);
            const float w2 = (float)(e2 & 0x7FFFu) * (1.0f / WFIX_SCALE);
            const float w3 = (float)(e3 & 0x7FFFu) * (1.0f / WFIX_SCALE);

            float2 a, b;
            a = __half22float2(*reinterpret_cast<const __half2*>(&p0.x));
            b = __half22float2(*reinterpret_cast<const __half2*>(&p0.y));
            acc0.x += w0 * a.x; acc0.y += w0 * a.y; acc0.z += w0 * b.x; acc0.w += w0 * b.y;
            a = __half22float2(*reinterpret_cast<const __half2*>(&p1.x));
            b = __half22float2(*reinterpret_cast<const __half2*>(&p1.y));
            acc1.x += w1 * a.x; acc1.y += w1 * a.y; acc1.z += w1 * b.x; acc1.w += w1 * b.y;
            a = __half22float2(*reinterpret_cast<const __half2*>(&p2.x));
            b = __half22float2(*reinterpret_cast<const __half2*>(&p2.y));
            acc0.x += w2 * a.x; acc0.y += w2 * a.y; acc0.z += w2 * b.x; acc0.w += w2 * b.y;
            a = __half22float2(*reinterpret_cast<const __half2*>(&p3.x));
            b = __half22float2(*reinterpret_cast<const __half2*>(&p3.y));
            acc1.x += w3 * a.x; acc1.y += w3 * a.y; acc1.z += w3 * b.x; acc1.w += w3 * b.y;
        }
        for (; j < n; j++) {
            const unsigned en = __shfl_sync(0xffffffffu, cw, j);
            const uint2 p = ldg_nc_u2(((const uint2*)(g_h + (size_t)(en >> 15) * 16)) + lane);
            const float wt = (float)(en & 0x7FFFu) * (1.0f / WFIX_SCALE);
            const float2 a = __half22float2(*reinterpret_cast<const __half2*>(&p.x));
            const float2 b = __half22float2(*reinterpret_cast<const __half2*>(&p.y));
            acc0.x += wt * a.x; acc0.y += wt * a.y; acc0.z += wt * b.x; acc0.w += wt * b.y;
        }
    }

    acc0.x += acc1.x; acc0.y += acc1.y; acc0.z += acc1.z; acc0.w += acc1.w;

    float* dst = out + (size_t)node * D + lane * 4;
    asm volatile("st.global.cs.v4.f32 [%0], {%1, %2, %3, %4};"
                 :: "l"(dst), "f"(acc0.x), "f"(acc0.y), "f"(acc0.z), "f"(acc0.w)
                 : "memory");

    if (lane == 0) g_cnt[node] = 0;  // clean for next replay
}

// ---------------------------------------------------------------------------
// spill fix-up + reset, single block (normally zero entries; spill keeps
// full fp32 weights).
// ---------------------------------------------------------------------------
__global__ __launch_bounds__(256) void spill_fix_kernel(float* __restrict__ out) {
    const int n = min(g_spill_cnt, MAX_SPILL);
    const int lane = threadIdx.x & 31;
    const int warp = threadIdx.x >> 5;

    for (int i = warp; i < n; i += 8) {
        const int4 s = g_spill[i];
        const uint2 p = ((const uint2*)(g_h + (size_t)s.y * 16))[lane];
        const float wt = __int_as_float(s.z);
        const float2 a = __half22float2(*reinterpret_cast<const __half2*>(&p.x));
        const float2 b = __half22float2(*reinterpret_cast<const __half2*>(&p.y));
        float* dst = out + (size_t)s.x * D + lane * 4;
        asm volatile("red.global.add.v4.f32 [%0], {%1, %2, %3, %4};"
                     :: "l"(dst), "f"(wt * a.x), "f"(wt * a.y),
                        "f"(wt * b.x), "f"(wt * b.y)
                     : "memory");
    }
    __syncthreads();
    if (threadIdx.x == 0) g_spill_cnt = 0;
}

// ---------------------------------------------------------------------------
// Launch: GEMM forked to side stream; origin does fill_direct, joins, agg,
// spill fix.
// ---------------------------------------------------------------------------
extern "C" void kernel_launch(void* const* d_in, const int* in_sizes, int n_in,
                              void* d_out, int out_size) {
    const float* node_emb    = (const float*)d_in[0];
    const int*   edges       = (const int*)d_in[1];
    const float* edge_weight = (const float*)d_in[2];
    const float* W           = (const float*)d_in[3];
    float*       out         = (float*)d_out;

    const int n_nodes = in_sizes[0] / D;
    const int n_edges = in_sizes[1] / 2;
    const int nq = n_edges >> 2;

    static cudaStream_t s2 = nullptr;
    static cudaEvent_t ev_fork = nullptr, ev_join = nullptr;
    if (s2 == nullptr) {
        cudaStreamCreateWithFlags(&s2, cudaStreamNonBlocking);
        cudaEventCreateWithFlags(&ev_fork, cudaEventDisableTiming);
        cudaEventCreateWithFlags(&ev_join, cudaEventDisableTiming);
    }

    // fork: GEMM on side stream
    cudaEventRecord(ev_fork, 0);
    cudaStreamWaitEvent(s2, ev_fork, 0);
    gemm_tc_kernel<<<(n_nodes + 127) / 128, 256, 0, s2>>>(node_emb, W, n_nodes);
    cudaEventRecord(ev_join, s2);

    // origin stream: single-pass bucketed CSR build (packed 4B entries)
    fill_direct_kernel<<<(nq + 255) / 256, 256, 0, 0>>>(edges, edge_weight,
                                                        n_edges, n_nodes);

    // join: agg needs g_h (side) + g_csr/g_cnt (origin)
    cudaStreamWaitEvent(0, ev_join, 0);
    const int agg_blocks = (n_nodes * 32 + 255) / 256;
    agg_kernel<<<agg_blocks, 256, 0, 0>>>(out, n_nodes);

    spill_fix_kernel<<<1, 256, 0, 0>>>(out);
}

// round 14
// speedup vs baseline: 1.1051x; 1.1051x over previous
#include <cuda_runtime.h>
#include <cuda_fp16.h>
#include <mma.h>
#include <cstdint>

using namespace nvcuda;

#define D 128
#define MAX_NODES 100032
#define SLOTS 96                 // Poisson(32) tail beyond 96: ~e^-41, spill-guarded
#define MAX_SPILL 65536

// ---- device scratch (static globals; allocation-free) ----
__device__ uint4 g_h[(size_t)MAX_NODES * 16];            // 25.6 MB, fp16 h
__device__ int2  g_csr[(size_t)MAX_NODES * SLOTS];       // 76.8 MB bucketed CSR
__device__ int   g_cnt[MAX_NODES];                       // degrees; re-zeroed by agg
__device__ int4  g_spill[MAX_SPILL];                     // (row, col, wbits, 0)
__device__ int   g_spill_cnt;                            // starts 0; reset by fix kernel

// ---------------------------------------------------------------------------
// Tensor-core GEMM: h = x @ W^T, fp16 in (converted in-flight), fp32 acc,
// fp16 out. 128x128 block tile, 8 warps (4M x 2N), 2x4 wmma frags per warp.
// ---------------------------------------------------------------------------
__global__ __launch_bounds__(256) void gemm_tc_kernel(const float* __restrict__ x,
                                                      const float* __restrict__ W,
                                                      int n_rows) {
    __shared__ __align__(32) __half ws[128][136];   // ws[n][k] = W[n][k]
    __shared__ __align__(32) __half xs[128][24];

    const int tid = threadIdx.x;
    const int warp = tid >> 5;
    const int lane = tid & 31;
    const int block_row = blockIdx.x * 128;
    const int wm = warp & 3;
    const int wn = warp >> 2;

    for (int q = tid; q < 128 * 32; q += 256) {
        const int r = q >> 5;
        const int c4 = q & 31;
        const float4 v = ((const float4*)(W + (size_t)r * D))[c4];
        const __half2 h0 = __floats2half2_rn(v.x, v.y);
        const __half2 h1 = __floats2half2_rn(v.z, v.w);
        uint2 pk;
        pk.x = *reinterpret_cast<const unsigned*>(&h0);
        pk.y = *reinterpret_cast<const unsigned*>(&h1);
        *(uint2*)&ws[r][c4 * 4] = pk;
    }

    wmma::fragment<wmma::accumulator, 16, 16, 16, float> c[2][4];
#pragma unroll
    for (int mi = 0; mi < 2; mi++)
#pragma unroll
        for (int ni = 0; ni < 4; ni++)
            wmma::fill_fragment(c[mi][ni], 0.f);

    for (int kt = 0; kt < 8; kt++) {
        const int k0 = kt * 16;
        __syncthreads();
        {
            const int row = tid >> 1;
            const int seg = (tid & 1) * 8;
            float4 v0 = make_float4(0.f, 0.f, 0.f, 0.f);
            float4 v1 = v0;
            const int gr = block_row + row;
            if (gr < n_rows) {
                const float* p = x + (size_t)gr * D + k0 + seg;
                v0 = *(const float4*)p;
                v1 = *(const float4*)(p + 4);
            }
            const __half2 a0 = __floats2half2_rn(v0.x, v0.y);
            const __half2 a1 = __floats2half2_rn(v0.z, v0.w);
            const __half2 a2 = __floats2half2_rn(v1.x, v1.y);
            const __half2 a3 = __floats2half2_rn(v1.z, v1.w);
            uint4 pk;
            pk.x = *reinterpret_cast<const unsigned*>(&a0);
            pk.y = *reinterpret_cast<const unsigned*>(&a1);
            pk.z = *reinterpret_cast<const unsigned*>(&a2);
            pk.w = *reinterpret_cast<const unsigned*>(&a3);
            *(uint4*)&xs[row][seg] = pk;
        }
        __syncthreads();

        wmma::fragment<wmma::matrix_a, 16, 16, 16, __half, wmma::row_major> a[2];
        wmma::fragment<wmma::matrix_b, 16, 16, 16, __half, wmma::col_major> b[4];
#pragma unroll
        for (int mi = 0; mi < 2; mi++)
            wmma::load_matrix_sync(a[mi], &xs[wm * 32 + mi * 16][0], 24);
#pragma unroll
        for (int ni = 0; ni < 4; ni++)
            wmma::load_matrix_sync(b[ni], &ws[wn * 64 + ni * 16][k0], 136);
#pragma unroll
        for (int mi = 0; mi < 2; mi++)
#pragma unroll
            for (int ni = 0; ni < 4; ni++)
                wmma::mma_sync(c[mi][ni], a[mi], b[ni], c[mi][ni]);
    }

    __syncthreads();
    float* stage = (float*)ws + warp * 320;  // 16x20 floats, ld=20 (80B, legal)
    __half* hbase = (__half*)g_h;
#pragma unroll
    for (int mi = 0; mi < 2; mi++) {
#pragma unroll
        for (int ni = 0; ni < 4; ni++) {
            wmma::store_matrix_sync(stage, c[mi][ni], 20, wmma::mem_row_major);
            __syncwarp();
            const int r = lane >> 1;
            const int c8 = (lane & 1) * 8;
            const float* sp = stage + r * 20 + c8;
            const __half2 h0 = __floats2half2_rn(sp[0], sp[1]);
            const __half2 h1 = __floats2half2_rn(sp[2], sp[3]);
            const __half2 h2 = __floats2half2_rn(sp[4], sp[5]);
            const __half2 h3 = __floats2half2_rn(sp[6], sp[7]);
            uint4 pk;
            pk.x = *reinterpret_cast<const unsigned*>(&h0);
            pk.y = *reinterpret_cast<const unsigned*>(&h1);
            pk.z = *reinterpret_cast<const unsigned*>(&h2);
            pk.w = *reinterpret_cast<const unsigned*>(&h3);
            const int gr = block_row + wm * 32 + mi * 16 + r;
            const int col = wn * 64 + ni * 16 + c8;
            if (gr < n_rows)
                *(uint4*)(hbase + (size_t)gr * D + col) = pk;
            __syncwarp();
        }
    }
}

// ---------------------------------------------------------------------------
// fill_direct: single-pass bucketed CSR build, 8B int2 entries (R12 layout —
// 4B packing regressed). Grid-stride x2: 8 edges per thread for deeper
// independent atomic->store chains (latency hiding).
// ---------------------------------------------------------------------------
__device__ __forceinline__ void fill_one(int row, int col, float w, int n_nodes) {
    if ((unsigned)row >= (unsigned)n_nodes || (unsigned)col >= (unsigned)n_nodes)
        return;
    const int pos = atomicAdd(&g_cnt[row], 1);
    if (pos < SLOTS) {
        int2* dst = &g_csr[(size_t)row * SLOTS + pos];
        asm volatile("st.global.cs.v2.u32 [%0], {%1, %2};"
                     :: "l"(dst), "r"(col), "r"(__float_as_int(w)) : "memory");
    } else {
        const int sp = atomicAdd(&g_spill_cnt, 1);
        if (sp < MAX_SPILL)
            g_spill[sp] = make_int4(row, col, __float_as_int(w), 0);
    }
}

__global__ __launch_bounds__(256) void fill_direct_kernel(const int* __restrict__ edges,
                                                          const float* __restrict__ wts,
                                                          int n_edges, int n_nodes) {
    const int nq = n_edges >> 2;
    const int stride = gridDim.x * blockDim.x;
    for (int q = blockIdx.x * blockDim.x + threadIdx.x; q < nq; q += stride) {
        const int4 r = ((const int4*)edges)[q];
        const int4 c = ((const int4*)(edges + n_edges))[q];
        const float4 w4 = ((const float4*)wts)[q];
        fill_one(r.x, c.x, w4.x, n_nodes);
        fill_one(r.y, c.y, w4.y, n_nodes);
        fill_one(r.z, c.z, w4.z, n_nodes);
        fill_one(r.w, c.w, w4.w, n_nodes);
    }
    if (blockIdx.x == 0 && (int)threadIdx.x < (n_edges & 3)) {
        const int e = ((n_edges >> 2) << 2) + threadIdx.x;
        fill_one(edges[e], edges[n_edges + e], wts[e], n_nodes);
    }
}

// ---------------------------------------------------------------------------
// agg: one warp per node, batch-32 int2 CSR loads + shfl, unroll x4, 2 accs.
// h gathers via ld.global.nc; out stores via st.global.cs.
// ---------------------------------------------------------------------------
__device__ __forceinline__ uint2 ldg_nc_u2(const uint2* p) {
    uint2 v;
    asm volatile("ld.global.nc.v2.u32 {%0, %1}, [%2];"
                 : "=r"(v.x), "=r"(v.y) : "l"(p));
    return v;
}

__global__ __launch_bounds__(256) void agg_kernel(float* __restrict__ out, int n_nodes) {
    const int lane = threadIdx.x & 31;
    const int node = (blockIdx.x * blockDim.x + threadIdx.x) >> 5;
    if (node >= n_nodes) return;

    const int cnt = g_cnt[node];
    const int e = min(cnt, SLOTS);
    const size_t base0 = (size_t)node * SLOTS;

    float4 acc0 = make_float4(0.f, 0.f, 0.f, 0.f);
    float4 acc1 = make_float4(0.f, 0.f, 0.f, 0.f);

    for (int base = 0; base < e; base += 32) {
        const int n = min(32, e - base);
        int2 cw = make_int2(0, 0);
        if (lane < n) cw = g_csr[base0 + base + lane];

        int j = 0;
        for (; j + 4 <= n; j += 4) {
            const int col0 = __shfl_sync(0xffffffffu, cw.x, j);
            const int w0i  = __shfl_sync(0xffffffffu, cw.y, j);
            const int col1 = __shfl_sync(0xffffffffu, cw.x, j + 1);
            const int w1i  = __shfl_sync(0xffffffffu, cw.y, j + 1);
            const int col2 = __shfl_sync(0xffffffffu, cw.x, j + 2);
            const int w2i  = __shfl_sync(0xffffffffu, cw.y, j + 2);
            const int col3 = __shfl_sync(0xffffffffu, cw.x, j + 3);
            const int w3i  = __shfl_sync(0xffffffffu, cw.y, j + 3);

            const uint2 p0 = ldg_nc_u2(((const uint2*)(g_h + (size_t)col0 * 16)) + lane);
            const uint2 p1 = ldg_nc_u2(((const uint2*)(g_h + (size_t)col1 * 16)) + lane);
            const uint2 p2 = ldg_nc_u2(((const uint2*)(g_h + (size_t)col2 * 16)) + lane);
            const uint2 p3 = ldg_nc_u2(((const uint2*)(g_h + (size_t)col3 * 16)) + lane);

            const float w0 = __int_as_float(w0i);
            const float w1 = __int_as_float(w1i);
            const float w2 = __int_as_float(w2i);
            const float w3 = __int_as_float(w3i);

            float2 a, b;
            a = __half22float2(*reinterpret_cast<const __half2*>(&p0.x));
            b = __half22float2(*reinterpret_cast<const __half2*>(&p0.y));
            acc0.x += w0 * a.x; acc0.y += w0 * a.y; acc0.z += w0 * b.x; acc0.w += w0 * b.y;
            a = __half22float2(*reinterpret_cast<const __half2*>(&p1.x));
            b = __half22float2(*reinterpret_cast<const __half2*>(&p1.y));
            acc1.x += w1 * a.x; acc1.y += w1 * a.y; acc1.z += w1 * b.x; acc1.w += w1 * b.y;
            a = __half22float2(*reinterpret_cast<const __half2*>(&p2.x));
            b = __half22float2(*reinterpret_cast<const __half2*>(&p2.y));
            acc0.x += w2 * a.x; acc0.y += w2 * a.y; acc0.z += w2 * b.x; acc0.w += w2 * b.y;
            a = __half22float2(*reinterpret_cast<const __half2*>(&p3.x));
            b = __half22float2(*reinterpret_cast<const __half2*>(&p3.y));
            acc1.x += w3 * a.x; acc1.y += w3 * a.y; acc1.z += w3 * b.x; acc1.w += w3 * b.y;
        }
        for (; j < n; j++) {
            const int col = __shfl_sync(0xffffffffu, cw.x, j);
            const int wi  = __shfl_sync(0xffffffffu, cw.y, j);
            const uint2 p = ldg_nc_u2(((const uint2*)(g_h + (size_t)col * 16)) + lane);
            const float wt = __int_as_float(wi);
            const float2 a = __half22float2(*reinterpret_cast<const __half2*>(&p.x));
            const float2 b = __half22float2(*reinterpret_cast<const __half2*>(&p.y));
            acc0.x += wt * a.x; acc0.y += wt * a.y; acc0.z += wt * b.x; acc0.w += wt * b.y;
        }
    }

    acc0.x += acc1.x; acc0.y += acc1.y; acc0.z += acc1.z; acc0.w += acc1.w;

    float* dst = out + (size_t)node * D + lane * 4;
    asm volatile("st.global.cs.v4.f32 [%0], {%1, %2, %3, %4};"
                 :: "l"(dst), "f"(acc0.x), "f"(acc0.y), "f"(acc0.z), "f"(acc0.w)
                 : "memory");

    if (lane == 0) g_cnt[node] = 0;  // clean for next replay
}

// ---------------------------------------------------------------------------
// spill fix-up + reset, single block (normally zero entries).
// ---------------------------------------------------------------------------
__global__ __launch_bounds__(256) void spill_fix_kernel(float* __restrict__ out) {
    const int n = min(g_spill_cnt, MAX_SPILL);
    const int lane = threadIdx.x & 31;
    const int warp = threadIdx.x >> 5;

    for (int i = warp; i < n; i += 8) {
        const int4 s = g_spill[i];
        const uint2 p = ((const uint2*)(g_h + (size_t)s.y * 16))[lane];
        const float wt = __int_as_float(s.z);
        const float2 a = __half22float2(*reinterpret_cast<const __half2*>(&p.x));
        const float2 b = __half22float2(*reinterpret_cast<const __half2*>(&p.y));
        float* dst = out + (size_t)s.x * D + lane * 4;
        asm volatile("red.global.add.v4.f32 [%0], {%1, %2, %3, %4};"
                     :: "l"(dst), "f"(wt * a.x), "f"(wt * a.y),
                        "f"(wt * b.x), "f"(wt * b.y)
                     : "memory");
    }
    __syncthreads();
    if (threadIdx.x == 0) g_spill_cnt = 0;
}

// ---------------------------------------------------------------------------
// Launch: GEMM forked to side stream; origin does fill_direct, joins, agg,
// spill fix.
// ---------------------------------------------------------------------------
extern "C" void kernel_launch(void* const* d_in, const int* in_sizes, int n_in,
                              void* d_out, int out_size) {
    const float* node_emb    = (const float*)d_in[0];
    const int*   edges       = (const int*)d_in[1];
    const float* edge_weight = (const float*)d_in[2];
    const float* W           = (const float*)d_in[3];
    float*       out         = (float*)d_out;

    const int n_nodes = in_sizes[0] / D;
    const int n_edges = in_sizes[1] / 2;
    const int nq = n_edges >> 2;

    static cudaStream_t s2 = nullptr;
    static cudaEvent_t ev_fork = nullptr, ev_join = nullptr;
    if (s2 == nullptr) {
        cudaStreamCreateWithFlags(&s2, cudaStreamNonBlocking);
        cudaEventCreateWithFlags(&ev_fork, cudaEventDisableTiming);
        cudaEventCreateWithFlags(&ev_join, cudaEventDisableTiming);
    }

    // fork: GEMM on side stream
    cudaEventRecord(ev_fork, 0);
    cudaStreamWaitEvent(s2, ev_fork, 0);
    gemm_tc_kernel<<<(n_nodes + 127) / 128, 256, 0, s2>>>(node_emb, W, n_nodes);
    cudaEventRecord(ev_join, s2);

    // origin stream: bucketed CSR build, 8 edges/thread (2 quads grid-stride)
    const int fill_blocks = (nq / 2 + 255) / 256;
    fill_direct_kernel<<<fill_blocks, 256, 0, 0>>>(edges, edge_weight,
                                                   n_edges, n_nodes);

    // join: agg needs g_h (side) + g_csr/g_cnt (origin)
    cudaStreamWaitEvent(0, ev_join, 0);
    const int agg_blocks = (n_nodes * 32 + 255) / 256;
    agg_kernel<<<agg_blocks, 256, 0, 0>>>(out, n_nodes);

    spill_fix_kernel<<<1, 256, 0, 0>>>(out);
}